// round 17
// baseline (speedup 1.0000x reference)
#include <cuda_runtime.h>
#include <cuda_bf16.h>
#include <math.h>
#include <stdint.h>

#define BB 4
#define CC 64
#define HH 96
#define WW 320
#define HP 97   // conv rows 0..96 (row 96 = top kernel row on x[95])

// Scratch (static device globals: allowed; no runtime allocation)
__device__ float g_conv[BB*CC*HP*WW];   // ~31.8 MB
__device__ float g_mid [BB*CC*HH*WW];   // ~31.5 MB
__device__ float g_T   [BB*CC*16*WW];   // ~5.2 MB

// Pre-split weights, fragment-ready: [co][tap][chunk][perm(ci16)] bf16
__device__ __align__(16) __nv_bfloat16 g_Wh[64*9*4*16];   // 73728 B
__device__ __align__(16) __nv_bfloat16 g_Wl[64*9*4*16];

// rows f_d-1, f_d for f = {1,12,22,33,44,54,65,76}
__constant__ int c_R16[16] = {0,1, 11,12, 21,22, 32,33, 43,44, 53,54, 64,65, 75,76};

#define MMA_BF16(d, a0, a1, a2, a3, b0, b1)                                  \
    asm volatile(                                                            \
        "mma.sync.aligned.m16n8k16.row.col.f32.bf16.bf16.f32 "               \
        "{%0,%1,%2,%3}, {%4,%5,%6,%7}, {%8,%9}, {%0,%1,%2,%3};"              \
        : "+f"(d[0]), "+f"(d[1]), "+f"(d[2]), "+f"(d[3])                     \
        : "r"(a0), "r"(a1), "r"(a2), "r"(a3), "r"(b0), "r"(b1))

// pair-interleave permutation: word w0=k{0,1}, w1=k{8,9}, w2=k{2,3}, w3=k{10,11}, ...
__host__ __device__ __forceinline__ int perm16(int ci) {
    return ((ci & 6) << 1) | ((ci >> 3) << 1) | (ci & 1);
}

// ---------------------------------------------------------------------------
// Weight split precompute: RN hi/lo bf16, permuted fragment layout.
// ---------------------------------------------------------------------------
__global__ void wsplit_kernel(const float* __restrict__ wk)
{
    int idx = blockIdx.x * 256 + threadIdx.x;
    if (idx >= 64*9*64) return;
    int co  = idx / 576;
    int rem = idx - co * 576;
    int tap = rem / 64;
    int ci  = rem - tap * 64;
    float v = wk[((size_t)co * 64 + ci) * 9 + tap];
    __nv_bfloat16 h = __float2bfloat16(v);
    __nv_bfloat16 l = __float2bfloat16(v - __bfloat162float(h));
    int dst = ((co*9 + tap)*4 + (ci >> 4))*16 + perm16(ci & 15);
    g_Wh[dst] = h;
    g_Wl[dst] = l;
}

// ---------------------------------------------------------------------------
// conv3 as 9 shifted K=64 GEMMs on tensor cores (no im2col).
// Block: 4 output rows x 64 cols x 64 co. 8 warps = 4 co-groups x 2 n-halves.
// ci chunked by 16 (one k16 MMA step per tap). bf16 2-way split, 3 passes.
// grid = (WW/64=5, ceil(HP/4)=25, BB). Output rows 0..96 into g_conv.
// ---------------------------------------------------------------------------
__global__ __launch_bounds__(256, 2)
void conv3_mma_kernel(const float* __restrict__ in_ext)
{
    const float* in = in_ext ? in_ext : g_mid;

    // X strip: [6 rows][68 cols][stride 10 words: 8 real (16 permuted ci) + 2 pad]
    __shared__ __align__(16) uint16_t Xh[6*68*20];   // 16320 B
    __shared__ __align__(16) uint16_t Xl[6*68*20];   // 16320 B

    const int x0   = blockIdx.x * 64;
    const int y0   = blockIdx.y * 4;
    const int b    = blockIdx.z;
    const int tid  = threadIdx.x;
    const int w    = tid >> 5;
    const int lane = tid & 31;
    const int gq   = lane >> 2;             // 0..7
    const int c4   = lane & 3;              // 0..3
    const int cobase = (w >> 1) * 16;
    const int nb     = (w & 1) * 32;
    const int co_a   = cobase + gq;
    const int co_b   = co_a + 8;

    const uint2* WhA = (const uint2*)g_Wh;  // u64 granules: {a0,a2} / {a1,a3}
    const uint2* WlA = (const uint2*)g_Wl;

    float acc[16][4];
    #pragma unroll
    for (int i = 0; i < 16; i++)
        #pragma unroll
        for (int e = 0; e < 4; e++) acc[i][e] = 0.f;

    #pragma unroll 1
    for (int cw = 0; cw < 4; cw++) {        // ci chunk of 16
        const int ci0 = cw * 16;
        // ---- stage raw strip: 16ci x 6rows x 66cols, truncation split ----
        #pragma unroll 1
        for (int idx = tid; idx < 6336; idx += 256) {
            int ci_l = idx / 396;
            int rem  = idx - ci_l * 396;
            int r    = rem / 66;
            int c    = rem - r * 66;
            int gy = y0 - 1 + r, gx = x0 - 1 + c;
            float v = 0.f;
            if ((unsigned)gy < (unsigned)HH && (unsigned)gx < (unsigned)WW)
                v = in[((size_t)(b*CC + ci0 + ci_l) * HH + gy) * WW + gx];
            unsigned u = __float_as_uint(v);
            float hf = __uint_as_float(u & 0xFFFF0000u);
            __nv_bfloat16 l = __float2bfloat16(v - hf);
            int h_idx = (r*68 + c)*20 + perm16(ci_l);
            Xh[h_idx] = (uint16_t)(u >> 16);
            Xl[h_idx] = *(const uint16_t*)&l;
        }
        __syncthreads();

        // ---- 9 shifted tap-GEMMs, K=16 each, 3 split passes ----
        #pragma unroll
        for (int ky = 0; ky < 3; ky++) {
            #pragma unroll
            for (int kx = 0; kx < 3; kx++) {
                const int tap = ky*3 + kx;
                uint2 ha = WhA[ ((co_a*9 + tap)*4 + cw)*4 + c4 ];  // {a0,a2} hi
                uint2 hb = WhA[ ((co_b*9 + tap)*4 + cw)*4 + c4 ];  // {a1,a3} hi
                uint2 la = WlA[ ((co_a*9 + tap)*4 + cw)*4 + c4 ];
                uint2 lb = WlA[ ((co_b*9 + tap)*4 + cw)*4 + c4 ];
                #pragma unroll
                for (int ro = 0; ro < 4; ro++) {
                    const int rbase = (ro + ky)*68;
                    #pragma unroll
                    for (int cf = 0; cf < 4; cf++) {
                        const int col  = nb + cf*8 + gq + kx;
                        const int word = (rbase + col)*10 + 2*c4;
                        uint2 bh = *(const uint2*)((const char*)Xh + (size_t)word*4);
                        uint2 bl = *(const uint2*)((const char*)Xl + (size_t)word*4);
                        float* d = acc[ro*4 + cf];
                        MMA_BF16(d, ha.x, hb.x, ha.y, hb.y, bh.x, bh.y);  // hi*hi
                        MMA_BF16(d, ha.x, hb.x, ha.y, hb.y, bl.x, bl.y);  // hi*lo
                        MMA_BF16(d, la.x, lb.x, la.y, lb.y, bh.x, bh.y);  // lo*hi
                    }
                }
            }
        }
        __syncthreads();
    }

    // ---- epilogue ----
    #pragma unroll
    for (int ro = 0; ro < 4; ro++) {
        const int y = y0 + ro;
        if (y >= HP) continue;
        #pragma unroll
        for (int cf = 0; cf < 4; cf++) {
            const float* d = acc[ro*4 + cf];
            const int n0 = x0 + nb + cf*8 + 2*c4;
            *(float2*)&g_conv[((size_t)(b*CC + co_a) * HP + y) * WW + n0] =
                make_float2(d[0], d[1]);
            *(float2*)&g_conv[((size_t)(b*CC + co_b) * HP + y) * WW + n0] =
                make_float2(d[2], d[3]);
        }
    }
}

// ---------------------------------------------------------------------------
// Top-kernel-row conv T[r] at the 16 rows in c_R16 (fp32 exact correction).
// ci chunked by 8: 16 barriers, burst loads. grid = (10, 4, BB), 256 threads.
// ---------------------------------------------------------------------------
__global__ __launch_bounds__(256, 2)
void trow_kernel(const float* __restrict__ in_ext, const float* __restrict__ wk)
{
    const float* in = in_ext ? in_ext : g_mid;
    __shared__ __align__(16) float Xs4[8][4][34];   // 17408 B
    __shared__ __align__(16) float Ws3[8][3][64];   //  6144 B

    const int x0  = blockIdx.x * 32;
    const int rg  = blockIdx.y;
    const int b   = blockIdx.z;
    const int tid = threadIdx.x;
    const int cog = tid >> 5;
    const int lx  = tid & 31;

    float acc[8][4];
    #pragma unroll
    for (int i = 0; i < 8; i++)
        #pragma unroll
        for (int r = 0; r < 4; r++) acc[i][r] = 0.f;

    #pragma unroll 1
    for (int ci0 = 0; ci0 < CC; ci0 += 8) {
        for (int idx = tid; idx < 1088; idx += 256) {      // 8ci * 136
            int ci_l = idx / 136;
            int rem  = idx - ci_l * 136;
            int r = rem / 34, c = rem - r * 34;
            int gy = c_R16[rg*4 + r];
            int gx = x0 - 1 + c;
            float v = 0.f;
            if ((unsigned)gx < (unsigned)WW)
                v = in[((size_t)(b*CC + ci0 + ci_l) * HH + gy) * WW + gx];
            Xs4[ci_l][r][c] = v;
        }
        for (int idx = tid; idx < 1536; idx += 256) {      // 8ci * 192
            int ci_l = idx / 192;
            int rem  = idx - ci_l * 192;
            int co = rem / 3, kx = rem - co * 3;
            Ws3[ci_l][kx][co] = wk[((size_t)co*CC + ci0 + ci_l)*9 + kx];
        }
        __syncthreads();

        #pragma unroll 1
        for (int kk = 0; kk < 8; kk++) {
            #pragma unroll
            for (int rr = 0; rr < 4; rr++) {
                float xv[3] = { Xs4[kk][rr][lx], Xs4[kk][rr][lx+1], Xs4[kk][rr][lx+2] };
                #pragma unroll
                for (int kx = 0; kx < 3; kx++) {
                    const float4* wp = reinterpret_cast<const float4*>(&Ws3[kk][kx][0]) + cog*2;
                    float4 wa = wp[0], wb = wp[1];
                    float wv[8] = {wa.x, wa.y, wa.z, wa.w, wb.x, wb.y, wb.z, wb.w};
                    #pragma unroll
                    for (int i = 0; i < 8; i++)
                        acc[i][rr] = fmaf(wv[i], xv[kx], acc[i][rr]);
                }
            }
        }
        __syncthreads();
    }

    #pragma unroll
    for (int i = 0; i < 8; i++) {
        int co = cog*8 + i;
        #pragma unroll
        for (int rr = 0; rr < 4; rr++)
            g_T[((size_t)(b*CC + co) * 16 + rg*4 + rr) * WW + x0 + lx] = acc[i][rr];
    }
}

// ---------------------------------------------------------------------------
// Plane-blend + max + bias + relu. Sliding-window register carry: consecutive
// y share plane rows (v0_next = v1_prev) -> half the LDS + predicates.
// grid = (10, BB*CC), 256 threads.
// ---------------------------------------------------------------------------
__global__ __launch_bounds__(256)
void blend_kernel(const float* __restrict__ bias, float* __restrict__ out_ext)
{
    float* out = out_ext ? out_ext : g_mid;
    __shared__ float s[HP][32];

    const int x0  = blockIdx.x * 32;
    const int bc  = blockIdx.y;
    const int tid = threadIdx.x;
    const float* src = g_conv + (size_t)bc * HP * WW + x0;

    for (int idx = tid; idx < HP*32; idx += 256) {
        int r = idx >> 5, c = idx & 31;
        s[r][c] = src[(size_t)r * WW + c];
    }
    __syncthreads();

    const int fi[8]   = {1, 12, 22, 33, 44, 54, 65, 76};
    const float wf[8] = {0.52f, 0.16f, 0.80f, 0.44f, 0.08f, 0.72f, 0.36f, 0.0f};

    const int lx = tid & 31;
    const int ty = tid >> 5;                    // 0..7, each handles 12 rows
    const float bv = bias[bc & (CC - 1)];
    const int y_base = ty * 12;

    float vprev[8];
    #pragma unroll
    for (int d = 0; d < 8; d++) {
        int r0 = y_base + fi[d];
        vprev[d] = (r0 <= HH) ? s[r0][lx] : 0.f;
    }

    float* orow = &out[((size_t)bc * HH + y_base) * WW + x0 + lx];
    #pragma unroll 1
    for (int yy = 0; yy < 12; yy++) {
        const int y = y_base + yy;
        float m = -3.0e38f;
        #pragma unroll
        for (int d = 0; d < 8; d++) {
            int r1 = y + fi[d] + 1;
            float vb = (r1 <= HH) ? s[r1][lx] : 0.f;
            float v  = (1.f - wf[d]) * vprev[d] + wf[d] * vb;
            vprev[d] = vb;
            m = fmaxf(m, v);
        }
        if (y == 0) {
            // exact top-boundary correction: subtract K_top applied to warpedz[-1]
            m = -3.0e38f;
            #pragma unroll
            for (int d = 0; d < 8; d++) {
                float T0 = g_T[((size_t)bc * 16 + 2*d    ) * WW + x0 + lx];
                float T1 = g_T[((size_t)bc * 16 + 2*d + 1) * WW + x0 + lx];
                float v0 = s[fi[d]][lx]     - T0;
                float v1 = s[fi[d] + 1][lx] - T1;
                float v  = (1.f - wf[d]) * v0 + wf[d] * v1;
                m = fmaxf(m, v);
            }
        }
        *orow = fmaxf(m + bv, 0.f);
        orow += WW;
    }
}

// ---------------------------------------------------------------------------
extern "C" void kernel_launch(void* const* d_in, const int* in_sizes, int n_in,
                              void* d_out, int out_size)
{
    const float* x  = (const float*)d_in[0];
    const float* W1 = (const float*)d_in[1];
    const float* b1 = (const float*)d_in[2];
    const float* W2 = (const float*)d_in[3];
    const float* b2 = (const float*)d_in[4];
    float* out = (float*)d_out;

    dim3 gm(WW/64, (HP + 3) / 4, BB);   // 5 x 25 x 4
    dim3 gt(WW/32, 4, BB);              // 10 x 4 x 4
    dim3 gb(WW/32, BB*CC);              // 10 x 256

    // Layer 1
    wsplit_kernel   <<<144, 256>>>(W1);
    conv3_mma_kernel<<<gm, 256>>>(x);
    trow_kernel     <<<gt, 256>>>(x, W1);
    blend_kernel    <<<gb, 256>>>(b1, nullptr);   // -> g_mid (includes relu)
    // Layer 2
    wsplit_kernel   <<<144, 256>>>(W2);
    conv3_mma_kernel<<<gm, 256>>>(nullptr);       // in = g_mid
    trow_kernel     <<<gt, 256>>>(nullptr, W2);
    blend_kernel    <<<gb, 256>>>(b2, out);
}